// round 7
// baseline (speedup 1.0000x reference)
#include <cuda_runtime.h>
#include <math.h>
#include <stdint.h>

#define HH 1024
#define LL 128
#define VOCAB 50257
#define STAGE_BYTES 98304u              // 96KB per stage
#define STAGE_F (STAGE_BYTES / 4)
#define R4K 24                          // 4KB rows per stage
#define R8K 12                          // 8KB rows per stage
#define NCH5 ((VOCAB + R4K - 1) / R4K)  // 2095 out_W chunks

// ---------------- device scratch (no allocations allowed) ----------------
__device__ float g_scores[LL];
__device__ float g_attn[HH];
__device__ float g_gru_in[HH];
__device__ float g_gh[3 * HH];
__device__ float g_gi[3 * HH];
__device__ float g_bmax[256], g_bsum[256];
__device__ float g_lse;
__device__ unsigned g_flags[256];
__device__ unsigned g_rel[16];

__device__ __forceinline__ float warp_sum(float v) {
#pragma unroll
    for (int o = 16; o > 0; o >>= 1) v += __shfl_down_sync(0xffffffffu, v, o);
    return v;
}

__device__ __forceinline__ void grid_bar(int nb, int bid, int t, int lane,
                                         int wid, unsigned gen) {
    __syncthreads();
    if (t == 0) {
        __threadfence();
        ((volatile unsigned*)g_flags)[bid] = gen;
    }
    if (bid == 0 && wid == 0) {
        bool ok;
        do {
            ok = true;
            for (int i = lane; i < nb; i += 32)
                if (((volatile unsigned*)g_flags)[i] < gen) ok = false;
            ok = __all_sync(0xffffffffu, ok);
        } while (!ok);
        if (lane == 0) {
            __threadfence();
            ((volatile unsigned*)g_rel)[gen] = 1u;
        }
    }
    if (t == 0) {
        while (((volatile unsigned*)g_rel)[gen] == 0u) {}
        __threadfence();
    }
    __syncthreads();
}

__device__ __forceinline__ void lse_combine(float& M, float& S, float m2, float s2) {
    if (m2 == -INFINITY) return;
    if (m2 > M) { S = S * expf(M - m2) + s2; M = m2; }
    else        { S += s2 * expf(m2 - M); }
}

__device__ __forceinline__ uint32_t smem_u32(const void* p) {
    uint32_t a;
    asm("{ .reg .u64 tmp; cvta.to.shared.u64 tmp, %1; cvt.u32.u64 %0, tmp; }"
        : "=r"(a) : "l"(p));
    return a;
}

// one thread: arrive.expect_tx + bulk-copy bytes (in <=32KB pieces)
__device__ __forceinline__ void tma_issue(uint32_t mbar, uint32_t dst,
                                          const float* src, uint32_t bytes) {
    asm volatile("mbarrier.arrive.expect_tx.shared.b64 _, [%0], %1;"
                 :: "r"(mbar), "r"(bytes) : "memory");
    const char* s = (const char*)src;
    for (uint32_t c = 0; c < bytes; c += 32768u) {
        uint32_t sz = bytes - c;
        if (sz > 32768u) sz = 32768u;
        asm volatile("cp.async.bulk.shared::cluster.global.mbarrier::complete_tx::bytes"
                     " [%0], [%1], %2, [%3];"
                     :: "r"(dst + c), "l"(s + c), "r"(sz), "r"(mbar) : "memory");
    }
}

// all threads spin on parity
__device__ __forceinline__ void tma_wait(uint32_t mbar, unsigned parity) {
    uint32_t done;
    do {
        asm volatile("{ .reg .pred p;\n\t"
                     "mbarrier.try_wait.parity.shared.b64 p, [%1], %2;\n\t"
                     "selp.b32 %0, 1, 0, p; }"
                     : "=r"(done) : "r"(mbar), "r"(parity) : "memory");
    } while (!done);
}

__device__ __forceinline__ float dot4k(const float* row, const float* vec, int lane) {
    const float4* r4 = (const float4*)row;
    const float4* v4 = (const float4*)vec;
    float acc = 0.f;
#pragma unroll
    for (int i = 0; i < 8; i++) {
        const int idx = lane + 32 * i;
        const float4 a = r4[idx], b = v4[idx];
        acc += a.x*b.x + a.y*b.y + a.z*b.z + a.w*b.w;
    }
    return warp_sum(acc);
}

__device__ __forceinline__ float dot8k(const float* row, const float* vec, int lane) {
    const float4* r4 = (const float4*)row;
    const float4* v4 = (const float4*)vec;
    float acc = 0.f;
#pragma unroll
    for (int i = 0; i < 16; i++) {
        const int idx = lane + 32 * i;
        const float4 a = r4[idx], b = v4[idx];
        acc += a.x*b.x + a.y*b.y + a.z*b.z + a.w*b.w;
    }
    return warp_sum(acc);
}

extern __shared__ float s_dyn[];   // 2 stages x 96KB

__global__ void __launch_bounds__(1024, 1)
fused_decoder(const int* __restrict__ ids,
              const float* __restrict__ hidden,
              const float* __restrict__ enc,
              const float* __restrict__ emb,
              const float* __restrict__ attn_W,
              const float* __restrict__ attn_b,
              const float* __restrict__ comb_W,
              const float* __restrict__ comb_b,
              const float* __restrict__ W_ih,
              const float* __restrict__ W_hh,
              const float* __restrict__ b_ih,
              const float* __restrict__ b_hh,
              const float* __restrict__ out_W,
              const float* __restrict__ out_b,
              float* __restrict__ out) {
    const int nb = gridDim.x;
    const int t = threadIdx.x, wid = t >> 5, lane = t & 31, bid = blockIdx.x;

    __shared__ float s_vec[2 * HH];
    __shared__ float s_red[1024];
    __shared__ float s_w[LL];
    __shared__ float s_m[2];
    __shared__ float s_bm[32], s_bs[32];
    __shared__ __align__(8) uint64_t s_mbar[2];

    float* st0 = s_dyn;
    float* st1 = s_dyn + STAGE_F;
    const uint32_t mb0 = smem_u32(&s_mbar[0]);
    const uint32_t mb1 = smem_u32(&s_mbar[1]);
    const uint32_t sd0 = smem_u32(s_dyn);
    const uint32_t sd1 = sd0 + STAGE_BYTES;
    unsigned par0 = 0, par1 = 0;

    if (t == 0) {
        asm volatile("mbarrier.init.shared.b64 [%0], %1;" :: "r"(mb0), "r"(1) : "memory");
        asm volatile("mbarrier.init.shared.b64 [%0], %1;" :: "r"(mb1), "r"(1) : "memory");
        asm volatile("fence.proxy.async.shared::cta;" ::: "memory");
    }
    __syncthreads();

    // ---- prologue TMA: P0 matrices -> stage0, P3 matrix (constant) -> stage1
    if (t == 0) {
        if (bid < 128) {
            tma_issue(mb0, sd0, W_hh + (size_t)bid * R4K * HH, R4K * HH * 4u);
            tma_issue(mb1, sd1, W_ih + (size_t)bid * R4K * HH, R4K * HH * 4u);
        } else if (bid < 139) {
            const int c = bid - 128;
            const int n = min(R8K, LL - c * R8K);
            tma_issue(mb0, sd0, attn_W + (size_t)c * R8K * 2 * HH, (uint32_t)n * 2 * HH * 4u);
        }
    }

    // ---- s_vec = [q ; h]
    const size_t qb = (size_t)ids[0] * HH;
    if (t < 256)       ((float4*)s_vec)[t] = ((const float4*)(emb + qb))[t];
    else if (t < 512)  ((float4*)s_vec)[t] = ((const float4*)hidden)[t - 256];
    __syncthreads();

    // ---------------- P0: gh = W_hh@h + b_hh | attn scores -------------------
    if (bid < 128) {
        tma_wait(mb0, par0); par0 ^= 1;
        if (wid < R4K) {
            const float a = dot4k(st0 + wid * HH, s_vec + HH, lane);
            const int j = bid * R4K + wid;
            if (lane == 0) g_gh[j] = a + b_hh[j];
        }
    } else if (bid < 139) {
        tma_wait(mb0, par0); par0 ^= 1;
        const int c = bid - 128;
        const int n = min(R8K, LL - c * R8K);
        if (wid < n) {
            const float a = dot8k(st0 + wid * 2 * HH, s_vec, lane);
            const int l = c * R8K + wid;
            if (lane == 0) g_scores[l] = a + attn_b[l];
        }
    }
    __syncthreads();
    // stage0 free -> issue P2 matrix (constant)
    if (t == 0 && bid < 86) {
        const int n = min(R8K, HH - bid * R8K);
        tma_issue(mb0, sd0, comb_W + (size_t)bid * R8K * 2 * HH, (uint32_t)n * 2 * HH * 4u);
    }
    grid_bar(nb, bid, t, lane, wid, 1u);

    // ---------------- P1: softmax + attn_applied (blocks 0..7) ---------------
    if (bid < 8) {
        float sc = (t < LL) ? g_scores[t] : -INFINITY;
        if (t < LL) {
            float v = sc;
#pragma unroll
            for (int o = 16; o > 0; o >>= 1) v = fmaxf(v, __shfl_down_sync(0xffffffffu, v, o));
            if (lane == 0) s_bm[wid] = v;
        }
        __syncthreads();
        if (t == 0) s_m[0] = fmaxf(fmaxf(s_bm[0], s_bm[1]), fmaxf(s_bm[2], s_bm[3]));
        __syncthreads();
        float e = 0.f;
        if (t < LL) {
            e = expf(sc - s_m[0]);
            float v = warp_sum(e);
            if (lane == 0) s_bs[wid] = v;
        }
        __syncthreads();
        if (t == 0) s_m[1] = 1.f / (s_bs[0] + s_bs[1] + s_bs[2] + s_bs[3]);
        __syncthreads();
        if (t < LL) {
            s_w[t] = e * s_m[1];
            if (bid == 0) out[VOCAB + HH + t] = s_w[t];
        }
        __syncthreads();
        const int col = t & 127, lg = t >> 7;
        const int colg = bid * 128 + col;
        float acc = 0.f;
#pragma unroll
        for (int k = 0; k < 16; k++) {
            const int l = lg * 16 + k;
            acc += s_w[l] * enc[(size_t)l * HH + colg];
        }
        s_red[t] = acc;
        __syncthreads();
        if (t < 128) {
            float a = 0.f;
#pragma unroll
            for (int k = 0; k < 8; k++) a += s_red[t + 128 * k];
            g_attn[colg] = a;
        }
    }
    grid_bar(nb, bid, t, lane, wid, 2u);

    // ---------------- P2: gru_in = relu([q; attn] @ comb_W.T + b) ------------
    if (t < 256) ((float4*)s_vec)[256 + t] = ((const float4*)g_attn)[t];
    __syncthreads();
    if (bid < 86) {
        tma_wait(mb0, par0); par0 ^= 1;
        const int n = min(R8K, HH - bid * R8K);
        if (wid < n) {
            const float a = dot8k(st0 + wid * 2 * HH, s_vec, lane);
            const int j = bid * R8K + wid;
            if (lane == 0) g_gru_in[j] = fmaxf(a + comb_b[j], 0.f);
        }
        __syncthreads();
    }
    grid_bar(nb, bid, t, lane, wid, 3u);

    // ---------------- P3: gi = W_ih @ gru_in ---------------------------------
    if (t < 256) ((float4*)s_vec)[t] = ((const float4*)g_gru_in)[t];
    __syncthreads();
    if (bid < 128) {
        tma_wait(mb1, par1); par1 ^= 1;
        if (wid < R4K) {
            const float a = dot4k(st1 + wid * HH, s_vec, lane);
            const int j = bid * R4K + wid;
            if (lane == 0) g_gi[j] = a;   // b_ih folded into P4
        }
        __syncthreads();
    }
    // both stages free -> issue out_W chunks 0 and 1 (overlaps barrier + P4)
    if (t == 0) {
        {
            const int r0 = bid * R4K;
            const int n = min(R4K, VOCAB - r0);
            tma_issue(mb0, sd0, out_W + (size_t)r0 * HH, (uint32_t)n * HH * 4u);
        }
        {
            const int r0 = (bid + nb) * R4K;
            const int n = min(R4K, VOCAB - r0);
            tma_issue(mb1, sd1, out_W + (size_t)r0 * HH, (uint32_t)n * HH * 4u);
        }
    }
    grid_bar(nb, bid, t, lane, wid, 4u);

    // ---------------- P4 (per-block): gate math -> s_vec[0:H] = h_new --------
    {
        const int j = t;
        const float ir  = g_gi[j]          + b_ih[j];
        const float iz  = g_gi[j + HH]     + b_ih[j + HH];
        const float inn = g_gi[j + 2 * HH] + b_ih[j + 2 * HH];
        const float hr  = g_gh[j];
        const float hz  = g_gh[j + HH];
        const float hn  = g_gh[j + 2 * HH];
        const float hv  = hidden[j];
        const float r = 1.f / (1.f + expf(-(ir + hr)));
        const float z = 1.f / (1.f + expf(-(iz + hz)));
        const float n = tanhf(inn + r * hn);
        const float hnew = (1.f - z) * n + z * hv;
        s_vec[j] = hnew;
        if (bid == 0) out[VOCAB + j] = hnew;
    }
    __syncthreads();

    // ---------------- P5: logits via TMA double-buffered pipeline ------------
    float m = -INFINITY, s = 0.f;
    for (int k = 0;; k++) {
        const int c = bid + k * nb;
        if (c >= NCH5) break;
        const int r0 = c * R4K;
        const int n = min(R4K, VOCAB - r0);
        const uint32_t mb = (k & 1) ? mb1 : mb0;
        float* stg = (k & 1) ? st1 : st0;
        unsigned& par = (k & 1) ? par1 : par0;
        tma_wait(mb, par); par ^= 1;
        if (wid < n) {
            const float a = dot4k(stg + wid * HH, s_vec, lane);
            const int row = r0 + wid;
            if (lane == 0) {
                const float lg = a + out_b[row];
                out[row] = lg;
                lse_combine(m, s, lg, 1.f);
            }
        }
        __syncthreads();
        const int c2 = bid + (k + 2) * nb;
        if (t == 0 && c2 < NCH5) {
            const int rr = c2 * R4K;
            const int nn = min(R4K, VOCAB - rr);
            tma_issue(mb, (k & 1) ? sd1 : sd0, out_W + (size_t)rr * HH,
                      (uint32_t)nn * HH * 4u);
        }
    }
    if (lane == 0) { s_bm[wid] = m; s_bs[wid] = s; }
    __syncthreads();
    if (wid == 0) {
        float M = s_bm[lane], S = s_bs[lane];
#pragma unroll
        for (int o = 16; o > 0; o >>= 1) {
            float m2 = __shfl_down_sync(0xffffffffu, M, o);
            float s2 = __shfl_down_sync(0xffffffffu, S, o);
            lse_combine(M, S, m2, s2);
        }
        if (lane == 0) { g_bmax[bid] = M; g_bsum[bid] = S; }
    }
    grid_bar(nb, bid, t, lane, wid, 5u);

    // ---------------- P6: global LSE -----------------------------------------
    if (bid == 0 && wid == 0) {
        float M = -INFINITY, S = 0.f;
        for (int i = lane; i < nb; i += 32) lse_combine(M, S, g_bmax[i], g_bsum[i]);
#pragma unroll
        for (int o = 16; o > 0; o >>= 1) {
            float m2 = __shfl_down_sync(0xffffffffu, M, o);
            float s2 = __shfl_down_sync(0xffffffffu, S, o);
            lse_combine(M, S, m2, s2);
        }
        if (lane == 0) g_lse = M + logf(S);
    }
    grid_bar(nb, bid, t, lane, wid, 6u);

    // ---------------- P7: log_probs = logits - lse ---------------------------
    {
        const float lse = g_lse;
        for (int i = bid * 1024 + t; i < VOCAB; i += nb * 1024) out[i] -= lse;
    }

    // ---------------- epilogue: reset barrier state --------------------------
    __syncthreads();
    if (t == 0) {
        __threadfence();
        ((volatile unsigned*)g_flags)[bid] = 7u;
    }
    if (bid == 0 && wid == 0) {
        bool ok;
        do {
            ok = true;
            for (int i = lane; i < nb; i += 32)
                if (((volatile unsigned*)g_flags)[i] < 7u) ok = false;
            ok = __all_sync(0xffffffffu, ok);
        } while (!ok);
        for (int i = lane; i < nb; i += 32) ((volatile unsigned*)g_flags)[i] = 0u;
        if (lane < 16) ((volatile unsigned*)g_rel)[lane] = 0u;
    }
}

extern "C" void kernel_launch(void* const* d_in, const int* in_sizes, int n_in,
                              void* d_out, int out_size) {
    const int*   ids    = (const int*)  d_in[0];
    const float* hidden = (const float*)d_in[1];
    const float* enc    = (const float*)d_in[2];
    const float* emb    = (const float*)d_in[3];
    const float* attn_W = (const float*)d_in[4];
    const float* attn_b = (const float*)d_in[5];
    const float* comb_W = (const float*)d_in[6];
    const float* comb_b = (const float*)d_in[7];
    const float* W_ih   = (const float*)d_in[8];
    const float* W_hh   = (const float*)d_in[9];
    const float* b_ih   = (const float*)d_in[10];
    const float* b_hh   = (const float*)d_in[11];
    const float* out_W  = (const float*)d_in[12];
    const float* out_b  = (const float*)d_in[13];
    float* out = (float*)d_out;

    int dev = 0, nsm = 148;
    cudaGetDevice(&dev);
    cudaDeviceGetAttribute(&nsm, cudaDevAttrMultiProcessorCount, dev);

    const int smem_bytes = 2 * STAGE_BYTES;   // 192 KB dynamic
    cudaFuncSetAttribute(fused_decoder,
                         cudaFuncAttributeMaxDynamicSharedMemorySize, smem_bytes);

    fused_decoder<<<nsm, 1024, smem_bytes>>>(ids, hidden, enc, emb, attn_W, attn_b,
                                             comb_W, comb_b, W_ih, W_hh, b_ih, b_hh,
                                             out_W, out_b, out);
}

// round 8
// speedup vs baseline: 1.1507x; 1.1507x over previous
#include <cuda_runtime.h>
#include <math.h>

#define HH 1024
#define LL 128
#define VOCAB 50257
#define NTHR 512

// ---------------- device scratch (no allocations allowed) ----------------
__device__ float g_scores[LL];
__device__ float g_attn[HH];
__device__ float g_gru_in[HH];
__device__ float g_gh[3 * HH];
__device__ float g_gi[3 * HH];
__device__ float g_bmax[256], g_bsum[256];
__device__ float g_lse;
__device__ unsigned g_flags[256];
__device__ unsigned g_rel[16];

__device__ __forceinline__ float warp_sum(float v) {
#pragma unroll
    for (int o = 16; o > 0; o >>= 1) v += __shfl_down_sync(0xffffffffu, v, o);
    return v;
}

__device__ __forceinline__ void grid_bar(int nb, int bid, int t, int lane,
                                         int wid, unsigned gen) {
    __syncthreads();
    if (t == 0) {
        __threadfence();
        ((volatile unsigned*)g_flags)[bid] = gen;
    }
    if (bid == 0 && wid == 0) {
        bool ok;
        do {
            ok = true;
            for (int i = lane; i < nb; i += 32)
                if (((volatile unsigned*)g_flags)[i] < gen) ok = false;
            ok = __all_sync(0xffffffffu, ok);
        } while (!ok);
        if (lane == 0) {
            __threadfence();
            ((volatile unsigned*)g_rel)[gen] = 1u;
        }
    }
    if (t == 0) {
        while (((volatile unsigned*)g_rel)[gen] == 0u) {}
        __threadfence();
    }
    __syncthreads();
}

__device__ __forceinline__ void lse_combine(float& M, float& S, float m2, float s2) {
    if (m2 == -INFINITY) return;
    if (m2 > M) { S = S * expf(M - m2) + s2; M = m2; }
    else        { S += s2 * expf(m2 - M); }
}

__global__ void __launch_bounds__(NTHR, 1)
fused_decoder(const int* __restrict__ ids,
              const float* __restrict__ hidden,
              const float* __restrict__ enc,
              const float* __restrict__ emb,
              const float* __restrict__ attn_W,
              const float* __restrict__ attn_b,
              const float* __restrict__ comb_W,
              const float* __restrict__ comb_b,
              const float* __restrict__ W_ih,
              const float* __restrict__ W_hh,
              const float* __restrict__ b_ih,
              const float* __restrict__ b_hh,
              const float* __restrict__ out_W,
              const float* __restrict__ out_b,
              float* __restrict__ out) {
    const int nb = gridDim.x;
    const int t = threadIdx.x, wid = t >> 5, lane = t & 31, bid = blockIdx.x;
    const int gw = wid * nb + bid;          // warp-major global warp id
    const int wg = bid * 16 + wid;          // block-major global warp id
    const int totW = nb * 16;               // total warps

    __shared__ float s_vec[2 * HH];         // phase-dependent operand vectors
    __shared__ float s_red[NTHR];
    __shared__ float s_w[LL];
    __shared__ float s_m[2];
    __shared__ float s_bm[16], s_bs[16];

    // s_vec = [q ; hidden]
    const size_t qb = (size_t)ids[0] * HH;
    if (t < 256)      ((float4*)s_vec)[t] = ((const float4*)(emb + qb))[t];
    else              ((float4*)s_vec)[t] = ((const float4*)hidden)[t - 256];
    __syncthreads();

    // -------- P0: gh rows (3072) + attention scores (128), all warps --------
    for (int task = gw; task < 3 * HH + LL; task += totW) {
        if (task < 3 * HH) {
            const float4* r4 = (const float4*)(W_hh + (size_t)task * HH);
            const float4* v4 = (const float4*)(s_vec + HH);
            float acc = 0.f;
#pragma unroll
            for (int i = 0; i < 8; i++) {
                const int idx = lane + 32 * i;
                const float4 a = r4[idx], b = v4[idx];
                acc += a.x*b.x + a.y*b.y + a.z*b.z + a.w*b.w;
            }
            acc = warp_sum(acc);
            if (lane == 0) g_gh[task] = acc + b_hh[task];
        } else {
            const int l = task - 3 * HH;
            const float4* r4 = (const float4*)(attn_W + (size_t)l * 2 * HH);
            const float4* v4 = (const float4*)s_vec;
            float acc = 0.f;
#pragma unroll
            for (int i = 0; i < 16; i++) {
                const int idx = lane + 32 * i;
                const float4 a = r4[idx], b = v4[idx];
                acc += a.x*b.x + a.y*b.y + a.z*b.z + a.w*b.w;
            }
            acc = warp_sum(acc);
            if (lane == 0) g_scores[l] = acc + attn_b[l];
        }
    }
    grid_bar(nb, bid, t, lane, wid, 1u);

    // -------- P1: softmax + attn_applied (blocks 0..7) ----------------------
    if (bid < 8) {
        float sc = (t < LL) ? g_scores[t] : -INFINITY;
        if (t < LL) {
            float v = sc;
#pragma unroll
            for (int o = 16; o > 0; o >>= 1) v = fmaxf(v, __shfl_down_sync(0xffffffffu, v, o));
            if (lane == 0) s_bm[wid] = v;
        }
        __syncthreads();
        if (t == 0) s_m[0] = fmaxf(fmaxf(s_bm[0], s_bm[1]), fmaxf(s_bm[2], s_bm[3]));
        __syncthreads();
        float e = 0.f;
        if (t < LL) {
            e = expf(sc - s_m[0]);
            float v = warp_sum(e);
            if (lane == 0) s_bs[wid] = v;
        }
        __syncthreads();
        if (t == 0) s_m[1] = 1.f / (s_bs[0] + s_bs[1] + s_bs[2] + s_bs[3]);
        __syncthreads();
        if (t < LL) {
            s_w[t] = e * s_m[1];
            if (bid == 0) out[VOCAB + HH + t] = s_w[t];
        }
        __syncthreads();
        const int col = t & 127, lg = t >> 7;          // 4 groups of 32 l's
        const int colg = bid * 128 + col;
        float acc = 0.f;
#pragma unroll
        for (int k = 0; k < 32; k++) {
            const int l = lg * 32 + k;
            acc += s_w[l] * enc[(size_t)l * HH + colg];
        }
        s_red[t] = acc;
        __syncthreads();
        if (t < 128) {
            g_attn[colg] = s_red[t] + s_red[t + 128] + s_red[t + 256] + s_red[t + 384];
        }
    }
    grid_bar(nb, bid, t, lane, wid, 2u);

    // -------- P2: gru_in = relu([q; attn] @ comb_W.T + b), 1024 tasks -------
    if (t < 256) ((float4*)s_vec)[256 + t] = ((const float4*)g_attn)[t];
    __syncthreads();
    for (int task = gw; task < HH; task += totW) {
        const float4* r4 = (const float4*)(comb_W + (size_t)task * 2 * HH);
        const float4* v4 = (const float4*)s_vec;
        float acc = 0.f;
#pragma unroll
        for (int i = 0; i < 16; i++) {
            const int idx = lane + 32 * i;
            const float4 a = r4[idx], b = v4[idx];
            acc += a.x*b.x + a.y*b.y + a.z*b.z + a.w*b.w;
        }
        acc = warp_sum(acc);
        if (lane == 0) g_gru_in[task] = fmaxf(acc + comb_b[task], 0.f);
    }
    grid_bar(nb, bid, t, lane, wid, 3u);

    // -------- P3: gi rows (3072 tasks) ---------------------------------------
    if (t < 256) ((float4*)s_vec)[t] = ((const float4*)g_gru_in)[t];
    __syncthreads();
    for (int task = gw; task < 3 * HH; task += totW) {
        const float4* r4 = (const float4*)(W_ih + (size_t)task * HH);
        const float4* v4 = (const float4*)s_vec;
        float acc = 0.f;
#pragma unroll
        for (int i = 0; i < 8; i++) {
            const int idx = lane + 32 * i;
            const float4 a = r4[idx], b = v4[idx];
            acc += a.x*b.x + a.y*b.y + a.z*b.z + a.w*b.w;
        }
        acc = warp_sum(acc);
        if (lane == 0) g_gi[task] = acc;
    }
    grid_bar(nb, bid, t, lane, wid, 4u);

    // -------- P4 (per-block): GRU gates -> s_vec[0:H] = h_new ---------------
#pragma unroll
    for (int u = 0; u < 2; u++) {
        const int j = t + u * NTHR;
        const float ir  = g_gi[j]          + b_ih[j];
        const float iz  = g_gi[j + HH]     + b_ih[j + HH];
        const float inn = g_gi[j + 2 * HH] + b_ih[j + 2 * HH];
        const float r = 1.f / (1.f + expf(-(ir + g_gh[j])));
        const float z = 1.f / (1.f + expf(-(iz + g_gh[j + HH])));
        const float n = tanhf(inn + r * g_gh[j + 2 * HH]);
        const float hnew = (1.f - z) * n + z * hidden[j];
        s_vec[j] = hnew;
        if (bid == 0) out[VOCAB + j] = hnew;
    }
    __syncthreads();

    // -------- P5: logits GEMV — 4 consecutive rows per warp -----------------
    {
        float4 hv[8];
#pragma unroll
        for (int i = 0; i < 8; i++) hv[i] = ((const float4*)s_vec)[lane + 32 * i];

        float m = -INFINITY, s = 0.f;
        for (int r4 = wg * 4; r4 < VOCAB; r4 += totW * 4) {
            const int n = min(4, VOCAB - r4);
            if (n == 4) {
                const float4* w0 = (const float4*)(out_W + (size_t)r4 * HH);
                const float4* w1 = (const float4*)(out_W + (size_t)(r4 + 1) * HH);
                const float4* w2 = (const float4*)(out_W + (size_t)(r4 + 2) * HH);
                const float4* w3 = (const float4*)(out_W + (size_t)(r4 + 3) * HH);
                float a0 = 0.f, a1 = 0.f, a2 = 0.f, a3 = 0.f;
#pragma unroll
                for (int i = 0; i < 8; i++) {
                    const int idx = lane + 32 * i;
                    const float4 b = hv[i];
                    const float4 x0 = w0[idx];
                    const float4 x1 = w1[idx];
                    const float4 x2 = w2[idx];
                    const float4 x3 = w3[idx];
                    a0 += x0.x*b.x + x0.y*b.y + x0.z*b.z + x0.w*b.w;
                    a1 += x1.x*b.x + x1.y*b.y + x1.z*b.z + x1.w*b.w;
                    a2 += x2.x*b.x + x2.y*b.y + x2.z*b.z + x2.w*b.w;
                    a3 += x3.x*b.x + x3.y*b.y + x3.z*b.z + x3.w*b.w;
                }
                a0 = warp_sum(a0); a1 = warp_sum(a1);
                a2 = warp_sum(a2); a3 = warp_sum(a3);
                if (lane == 0) {
                    const float4 bb = *(const float4*)(out_b + r4);
                    const float l0 = a0 + bb.x, l1 = a1 + bb.y;
                    const float l2 = a2 + bb.z, l3 = a3 + bb.w;
                    out[r4]     = l0; out[r4 + 1] = l1;
                    out[r4 + 2] = l2; out[r4 + 3] = l3;
                    lse_combine(m, s, l0, 1.f);
                    lse_combine(m, s, l1, 1.f);
                    lse_combine(m, s, l2, 1.f);
                    lse_combine(m, s, l3, 1.f);
                }
            } else {
                for (int c = 0; c < n; c++) {
                    const float4* w0 = (const float4*)(out_W + (size_t)(r4 + c) * HH);
                    float a0 = 0.f;
#pragma unroll
                    for (int i = 0; i < 8; i++) {
                        const int idx = lane + 32 * i;
                        const float4 x0 = w0[idx], b = hv[i];
                        a0 += x0.x*b.x + x0.y*b.y + x0.z*b.z + x0.w*b.w;
                    }
                    a0 = warp_sum(a0);
                    if (lane == 0) {
                        const float l0 = a0 + out_b[r4 + c];
                        out[r4 + c] = l0;
                        lse_combine(m, s, l0, 1.f);
                    }
                }
            }
        }
        if (lane == 0) { s_bm[wid] = m; s_bs[wid] = s; }
        __syncthreads();
        if (wid == 0) {
            float M = (lane < 16) ? s_bm[lane] : -INFINITY;
            float S = (lane < 16) ? s_bs[lane] : 0.f;
#pragma unroll
            for (int o = 16; o > 0; o >>= 1) {
                float m2 = __shfl_down_sync(0xffffffffu, M, o);
                float s2 = __shfl_down_sync(0xffffffffu, S, o);
                lse_combine(M, S, m2, s2);
            }
            if (lane == 0) { g_bmax[bid] = M; g_bsum[bid] = S; }
        }
    }
    grid_bar(nb, bid, t, lane, wid, 5u);

    // -------- P6: global LSE -------------------------------------------------
    if (bid == 0 && wid == 0) {
        float M = -INFINITY, S = 0.f;
        for (int i = lane; i < nb; i += 32) lse_combine(M, S, g_bmax[i], g_bsum[i]);
#pragma unroll
        for (int o = 16; o > 0; o >>= 1) {
            float m2 = __shfl_down_sync(0xffffffffu, M, o);
            float s2 = __shfl_down_sync(0xffffffffu, S, o);
            lse_combine(M, S, m2, s2);
        }
        if (lane == 0) g_lse = M + logf(S);
    }
    grid_bar(nb, bid, t, lane, wid, 6u);

    // -------- P7: log_probs = logits - lse -----------------------------------
    {
        const float lse = g_lse;
        for (int i = bid * NTHR + t; i < VOCAB; i += nb * NTHR) out[i] -= lse;
    }

    // -------- epilogue: reset barrier state for next graph replay ------------
    __syncthreads();
    if (t == 0) {
        __threadfence();
        ((volatile unsigned*)g_flags)[bid] = 7u;
    }
    if (bid == 0 && wid == 0) {
        bool ok;
        do {
            ok = true;
            for (int i = lane; i < nb; i += 32)
                if (((volatile unsigned*)g_flags)[i] < 7u) ok = false;
            ok = __all_sync(0xffffffffu, ok);
        } while (!ok);
        for (int i = lane; i < nb; i += 32) ((volatile unsigned*)g_flags)[i] = 0u;
        if (lane < 16) ((volatile unsigned*)g_rel)[lane] = 0u;
    }
}

extern "C" void kernel_launch(void* const* d_in, const int* in_sizes, int n_in,
                              void* d_out, int out_size) {
    const int*   ids    = (const int*)  d_in[0];
    const float* hidden = (const float*)d_in[1];
    const float* enc    = (const float*)d_in[2];
    const float* emb    = (const float*)d_in[3];
    const float* attn_W = (const float*)d_in[4];
    const float* attn_b = (const float*)d_in[5];
    const float* comb_W = (const float*)d_in[6];
    const float* comb_b = (const float*)d_in[7];
    const float* W_ih   = (const float*)d_in[8];
    const float* W_hh   = (const float*)d_in[9];
    const float* b_ih   = (const float*)d_in[10];
    const float* b_hh   = (const float*)d_in[11];
    const float* out_W  = (const float*)d_in[12];
    const float* out_b  = (const float*)d_in[13];
    float* out = (float*)d_out;

    int dev = 0, nsm = 148;
    cudaGetDevice(&dev);
    cudaDeviceGetAttribute(&nsm, cudaDevAttrMultiProcessorCount, dev);

    fused_decoder<<<nsm, NTHR>>>(ids, hidden, enc, emb, attn_W, attn_b,
                                 comb_W, comb_b, W_ih, W_hh, b_ih, b_hh,
                                 out_W, out_b, out);
}